// round 14
// baseline (speedup 1.0000x reference)
#include <cuda_runtime.h>
#include <math.h>

typedef unsigned long long u64;

static constexpr int Bc   = 8;
static constexpr int NQ   = 512;
static constexpr int NKV  = 512;
static constexpr int Hc   = 16;
static constexpr int Dc   = 256;

// scratch (allocation-free rule: device globals)
__device__ float g_proj[Bc * NKV * Dc];   // 4 MB
__device__ float g_attn[Bc * NQ  * Dc];   // 4 MB

// ---------- packed f32x2 helpers ----------
__device__ __forceinline__ u64 pack2(float x, float y) {
    u64 d; asm("mov.b64 %0, {%1, %2};" : "=l"(d) : "f"(x), "f"(y)); return d;
}
__device__ __forceinline__ void unpack2(u64 v, float& x, float& y) {
    asm("mov.b64 {%0, %1}, %2;" : "=f"(x), "=f"(y) : "l"(v));
}
__device__ __forceinline__ u64 fma2(u64 a, u64 b, u64 c) {
    u64 d; asm("fma.rn.f32x2 %0, %1, %2, %3;" : "=l"(d) : "l"(a), "l"(b), "l"(c)); return d;
}
__device__ __forceinline__ float ex2f(float x) {
    float r; asm("ex2.approx.f32 %0, %1;" : "=f"(r) : "f"(x)); return r;
}
__device__ __forceinline__ void cp_async16(void* smem, const void* gptr) {
    unsigned saddr = (unsigned)__cvta_generic_to_shared(smem);
    asm volatile("cp.async.cg.shared.global [%0], [%1], 16;" :: "r"(saddr), "l"(gptr));
}
#define CP_COMMIT()  asm volatile("cp.async.commit_group;" ::: "memory")
#define CP_WAIT(N)   asm volatile("cp.async.wait_group %0;" :: "n"(N) : "memory")

// ============================================================
// GEMM (R13, proven 22.3us): C = A @ W^T + bias
// BM=128, BN=64, BK=16, 512 threads, double-buffered smem.
// ============================================================
__global__ __launch_bounds__(512)
void gemm_bias_kernel(const float* __restrict__ A, const float* __restrict__ W,
                      const float* __restrict__ bias, float* __restrict__ C,
                      int M, int N, int K)
{
    __shared__ float As[2][16][132];
    __shared__ float Bs[2][16][68];

    const int t  = threadIdx.x;
    const int tx = t & 15;
    const int ty = t >> 4;
    const int m0 = blockIdx.y * 128;
    const int n0 = blockIdx.x * 64;

    const int rA = t >> 2;
    const int pA = (t & 3) * 4;
    const bool wact = (t < 256);
    const int rW = (t >> 2) & 63;
    const int pW = (t & 3) * 4;

    u64 acc[2][4];
#pragma unroll
    for (int i = 0; i < 2; i++)
#pragma unroll
        for (int j = 0; j < 4; j++) acc[i][j] = pack2(0.f, 0.f);

    const float* aptr = A + (size_t)(m0 + rA) * K + pA;
    const float* wptr = W + (size_t)(n0 + rW) * K + pW;

    float4 a0 = *reinterpret_cast<const float4*>(aptr);
    float4 w0 = wact ? *reinterpret_cast<const float4*>(wptr) : make_float4(0,0,0,0);

    As[0][pA + 0][rA] = a0.x; As[0][pA + 1][rA] = a0.y;
    As[0][pA + 2][rA] = a0.z; As[0][pA + 3][rA] = a0.w;
    if (wact) {
        Bs[0][pW + 0][rW] = w0.x; Bs[0][pW + 1][rW] = w0.y;
        Bs[0][pW + 2][rW] = w0.z; Bs[0][pW + 3][rW] = w0.w;
    }
    a0 = *reinterpret_cast<const float4*>(aptr + 16);
    if (wact) w0 = *reinterpret_cast<const float4*>(wptr + 16);
    __syncthreads();

    const int NT = K / 16;
    for (int i = 0; i < NT; i++) {
        const int buf = i & 1;
        if (i < NT - 1) {
            As[buf ^ 1][pA + 0][rA] = a0.x; As[buf ^ 1][pA + 1][rA] = a0.y;
            As[buf ^ 1][pA + 2][rA] = a0.z; As[buf ^ 1][pA + 3][rA] = a0.w;
            if (wact) {
                Bs[buf ^ 1][pW + 0][rW] = w0.x; Bs[buf ^ 1][pW + 1][rW] = w0.y;
                Bs[buf ^ 1][pW + 2][rW] = w0.z; Bs[buf ^ 1][pW + 3][rW] = w0.w;
            }
        }
        if (i < NT - 2) {
            a0 = *reinterpret_cast<const float4*>(aptr + (i + 2) * 16);
            if (wact) w0 = *reinterpret_cast<const float4*>(wptr + (i + 2) * 16);
        }
#pragma unroll
        for (int kk = 0; kk < 16; kk++) {
            const u64* a2 = reinterpret_cast<const u64*>(&As[buf][kk][ty * 4]);
            u64 am0 = a2[0], am1 = a2[1];
            float4 bv = *reinterpret_cast<const float4*>(&Bs[buf][kk][tx * 4]);
            u64 bd[4] = {pack2(bv.x, bv.x), pack2(bv.y, bv.y),
                         pack2(bv.z, bv.z), pack2(bv.w, bv.w)};
#pragma unroll
            for (int j = 0; j < 4; j++) {
                acc[0][j] = fma2(am0, bd[j], acc[0][j]);
                acc[1][j] = fma2(am1, bd[j], acc[1][j]);
            }
        }
        __syncthreads();
    }

    float4 bv = *reinterpret_cast<const float4*>(bias + n0 + tx * 4);
#pragma unroll
    for (int i = 0; i < 2; i++) {
        float lo[4], hi[4];
#pragma unroll
        for (int j = 0; j < 4; j++) unpack2(acc[i][j], lo[j], hi[j]);
        float4 o0 = make_float4(lo[0] + bv.x, lo[1] + bv.y, lo[2] + bv.z, lo[3] + bv.w);
        float4 o1 = make_float4(hi[0] + bv.x, hi[1] + bv.y, hi[2] + bv.z, hi[3] + bv.w);
        *reinterpret_cast<float4*>(C + (size_t)(m0 + ty * 4 + 2 * i) * N + n0 + tx * 4) = o0;
        *reinterpret_cast<float4*>(C + (size_t)(m0 + ty * 4 + 2 * i + 1) * N + n0 + tx * 4) = o1;
    }
}

// ============================================================
// attn: BARRIER-FREE warp-private pipelines.
// 512 threads = 16 warps. Warp w: qt=w&3 (k-quarter), qs=w>>2 (8-query
// slice). Lanes: h=lane&15, qgl=lane>>4; qpt=4 -> thread covers queries
// qs*8 + qgl*4 + {0..3}, k in [qt*128, qt*128+128).
// Each warp: private double-buffered smem stages (feat KC=4 rows + msg
// + adj) fed by its own cp.async group stream. NO bar.sync in the loop.
// Epilogue: cross-quarter combine via smem + one __syncthreads.
// ============================================================
static constexpr int KCq    = 4;
static constexpr int FEAT_S = KCq * Dc;          // 1024 f per stage
static constexpr int MSG_S  = 8 * 68;            // 544 f per stage (68-f rows)
static constexpr int ADJ_S  = 8 * KCq;           // 32 ints per stage
static constexpr int FEAT_T = 16 * 2 * FEAT_S;   // 32768 f
static constexpr int MSG_T  = 16 * 2 * MSG_S;    // 17408 f
static constexpr int ADJ_T  = 16 * 2 * ADJ_S;    // 1024 ints
static constexpr int SMEM_ATTN = (FEAT_T + MSG_T + ADJ_T) * 4;   // 204800 B

__global__ __launch_bounds__(512)
void attn_kernel(const float* __restrict__ messages, const int* __restrict__ adj,
                 float* __restrict__ outp)
{
    extern __shared__ __align__(16) float smemF[];

    const int t    = threadIdx.x;
    const int w    = t >> 5;
    const int lane = t & 31;
    const int qt   = w & 3;            // k-quarter
    const int qs   = w >> 2;           // query slice (8 queries)
    const int h    = lane & 15;
    const int qgl  = lane >> 4;        // 0/1
    const int b    = blockIdx.y;
    const int qb0  = blockIdx.x * 32;
    const int kb   = qt * (NKV / 4);

    float* featW = smemF + w * (2 * FEAT_S);
    float* msgW  = smemF + FEAT_T + w * (2 * MSG_S);
    int*   adjW  = (int*)(smemF + FEAT_T + MSG_T) + w * (2 * ADJ_S);

    const float4* msgG  = (const float4*)(messages + (size_t)(b * NQ + qb0) * NKV * Hc);
    const int*    adjG  = adj + (size_t)(b * NQ + qb0) * NKV;
    const float4* proj4 = (const float4*)(g_proj + (size_t)b * NKV * Dc);

    float l[4]  = {0.f, 0.f, 0.f, 0.f};
    float s2[4] = {0.f, 0.f, 0.f, 0.f};
    u64 acc[4][8];
#pragma unroll
    for (int qi = 0; qi < 4; qi++)
#pragma unroll
        for (int j = 0; j < 8; j++) acc[qi][j] = pack2(0.f, 0.f);

    // warp-private stage loader: chunk c (4 k-rows) into slot s
    auto load_stage = [&](int c, int s) {
        const int k0 = kb + c * KCq;
        float* fb = featW + s * FEAT_S;
#pragma unroll
        for (int i = 0; i < 8; i++) {          // 256 f4 / 32 lanes
            int lin = lane + i * 32;
            int kk = lin >> 6, g = lin & 63;
            int hh = g >> 2, j = g & 3;
            int dstf4 = j * (KCq * 16) + kk * 16 + (hh ^ (2 * j));
            cp_async16(fb + dstf4 * 4, &proj4[(size_t)(k0 + kk) * 64 + g]);
        }
        float* mb = msgW + s * MSG_S;
#pragma unroll
        for (int i = 0; i < 4; i++) {          // 128 f4 / 32 lanes
            int lin = lane + i * 32;
            int ql = lin >> 4;                 // 0..7
            int kk = (lin >> 2) & 3;
            int hq = lin & 3;
            cp_async16(mb + ql * 68 + kk * 16 + hq * 4,
                       &msgG[((size_t)(qs * 8 + ql) * NKV + k0 + kk) * 4 + hq]);
        }
        if (lane < 8) {                        // 8 int4 granules
            cp_async16(adjW + s * ADJ_S + lane * 4,
                       adjG + (size_t)(qs * 8 + lane) * NKV + k0);
        }
        CP_COMMIT();
    };

    const float L2E = 1.4426950408889634f;
    const int NCI = (NKV / 4) / KCq;   // 32 chunks

    load_stage(0, 0);
    load_stage(1, 1);

    for (int ci = 0; ci < NCI; ci++) {
        const int s = ci & 1;
        CP_WAIT(1);                // stage ci landed (ci+1 may be in flight)
        __syncwarp();

        const float* fb = featW + s * FEAT_S;
        const float* mb = msgW  + s * MSG_S;
        const int*   ab = adjW  + s * ADJ_S;

        int4 av[4];
#pragma unroll
        for (int qi = 0; qi < 4; qi++)
            av[qi] = *reinterpret_cast<const int4*>(&ab[(qgl * 4 + qi) * 4]);

#pragma unroll
        for (int u = 0; u < 4; u++) {
            u64 f[8];
#pragma unroll
            for (int j = 0; j < 4; j++) {
                float4 fv = *reinterpret_cast<const float4*>(
                    &fb[(j * (KCq * 16) + u * 16 + (h ^ (2 * j))) * 4]);
                f[2 * j]     = pack2(fv.x, fv.y);
                f[2 * j + 1] = pack2(fv.z, fv.w);
            }
#pragma unroll
            for (int qi = 0; qi < 4; qi++) {
                float mv = mb[(qgl * 4 + qi) * 68 + u * 16 + h];
                int a = (&av[qi].x)[u];
                float lg = fmaf(mv, L2E, (a > 0) ? 0.f : -2e9f);
                float p = ex2f(lg);
                l[qi] += p;
                s2[qi] = fmaf(p, p, s2[qi]);
                u64 pp = pack2(p, p);
#pragma unroll
                for (int j = 0; j < 8; j++)
                    acc[qi][j] = fma2(pp, f[j], acc[qi][j]);
            }
        }
        // issue next fetch into the slot just consumed (reads are already
        // register-resident: fma2s scoreboard-waited on every LDS above)
        if (ci + 2 < NCI) load_stage(ci + 2, s);
        else              CP_COMMIT();          // keep group accounting aligned
    }

    // ---- combine quarters via smem (overlay on feat region) ----
    __syncthreads();
    float* redS = smemF;   // 12 warps * 32 lanes * 72 f = 27648 f <= FEAT_T
    if (qt > 0) {
        float* sp = redS + (((qt - 1) * 4 + qs) * 32 + lane) * 72;
#pragma unroll
        for (int qi = 0; qi < 4; qi++) {
#pragma unroll
            for (int j = 0; j < 8; j++)
                unpack2(acc[qi][j], sp[qi * 18 + 2 * j], sp[qi * 18 + 2 * j + 1]);
            sp[qi * 18 + 16] = l[qi];
            sp[qi * 18 + 17] = s2[qi];
        }
    }
    __syncthreads();
    if (qt == 0) {
#pragma unroll
        for (int qi = 0; qi < 4; qi++) {
            float v[16];
#pragma unroll
            for (int j = 0; j < 8; j++) unpack2(acc[qi][j], v[2 * j], v[2 * j + 1]);
            float lsum = l[qi], s2sum = s2[qi];
#pragma unroll
            for (int r = 0; r < 3; r++) {
                const float* sp = redS + (((r * 4 + qs) * 32 + lane)) * 72 + qi * 18;
#pragma unroll
                for (int j = 0; j < 16; j++) v[j] += sp[j];
                lsum  += sp[16];
                s2sum += sp[17];
            }
            float wsc = sqrtf(s2sum) / (lsum * lsum);
            int q = qb0 + qs * 8 + qgl * 4 + qi;
            float* o = outp + (size_t)(b * NQ + q) * Dc + h * 16;
#pragma unroll
            for (int j = 0; j < 4; j++) {
                float4 ov = make_float4(v[4*j] * wsc, v[4*j+1] * wsc,
                                        v[4*j+2] * wsc, v[4*j+3] * wsc);
                *reinterpret_cast<float4*>(o + 4 * j) = ov;
            }
        }
    }
}

// ============================================================
extern "C" void kernel_launch(void* const* d_in, const int* in_sizes, int n_in,
                              void* d_out, int out_size)
{
    const float* v_inv    = (const float*)d_in[0];
    const float* messages = (const float*)d_in[1];
    const int*   adjm     = (const int*)d_in[2];
    const float* W_in     = (const float*)d_in[3];
    const float* b_in     = (const float*)d_in[4];
    const float* W_out    = (const float*)d_in[5];
    const float* b_out    = (const float*)d_in[6];
    float* out = (float*)d_out;

    float *p_proj = nullptr, *p_attn = nullptr;
    cudaGetSymbolAddress((void**)&p_proj, g_proj);
    cudaGetSymbolAddress((void**)&p_attn, g_attn);

    cudaFuncSetAttribute(attn_kernel, cudaFuncAttributeMaxDynamicSharedMemorySize, SMEM_ATTN);

    // 1) proj = v_inv @ W_in^T + b_in      [4096 x 256]
    {
        dim3 grid(Dc / 64, (Bc * NKV) / 128);
        gemm_bias_kernel<<<grid, 512>>>(v_inv, W_in, b_in, p_proj, Bc * NKV, Dc, Dc);
    }
    // 2) fused attention -> g_attn         [4096 x 256]
    {
        dim3 grid(NQ / 32, Bc);
        attn_kernel<<<grid, 512, SMEM_ATTN>>>(messages, adjm, p_attn);
    }
    // 3) out = g_attn @ W_out^T + b_out
    {
        dim3 grid(Dc / 64, (Bc * NQ) / 128);
        gemm_bias_kernel<<<grid, 512>>>(p_attn, W_out, b_out, out, Bc * NQ, Dc, Dc);
    }
}

// round 17
// speedup vs baseline: 1.8357x; 1.8357x over previous
#include <cuda_runtime.h>
#include <cuda_bf16.h>
#include <math.h>
#include <cstdint>

typedef unsigned long long u64;

static constexpr int Bc   = 8;
static constexpr int NQ   = 512;
static constexpr int NKV  = 512;
static constexpr int Hc   = 16;
static constexpr int Dc   = 256;

// scratch (allocation-free rule: device globals)
__device__ float g_proj[Bc * NKV * Dc];               // 4 MB
__device__ float g_attn[Bc * NQ  * Dc];               // 4 MB
__device__ __nv_bfloat16 g_wh[2 * Dc * Dc];           // W_in/W_out hi
__device__ __nv_bfloat16 g_wl[2 * Dc * Dc];           // W_in/W_out lo
__device__ __nv_bfloat16 g_ah[Bc * NQ * Dc];          // A hi (2 MB)
__device__ __nv_bfloat16 g_al[Bc * NQ * Dc];          // A lo (2 MB)

// ---------- helpers ----------
__device__ __forceinline__ u64 pack2(float x, float y) {
    u64 d; asm("mov.b64 %0, {%1, %2};" : "=l"(d) : "f"(x), "f"(y)); return d;
}
__device__ __forceinline__ void unpack2(u64 v, float& x, float& y) {
    asm("mov.b64 {%0, %1}, %2;" : "=f"(x), "=f"(y) : "l"(v));
}
__device__ __forceinline__ u64 fma2(u64 a, u64 b, u64 c) {
    u64 d; asm("fma.rn.f32x2 %0, %1, %2, %3;" : "=l"(d) : "l"(a), "l"(b), "l"(c)); return d;
}
__device__ __forceinline__ float ex2f(float x) {
    float r; asm("ex2.approx.f32 %0, %1;" : "=f"(r) : "f"(x)); return r;
}
__device__ __forceinline__ void cp_async16(void* smem, const void* gptr) {
    unsigned saddr = (unsigned)__cvta_generic_to_shared(smem);
    asm volatile("cp.async.cg.shared.global [%0], [%1], 16;" :: "r"(saddr), "l"(gptr));
}
#define CP_COMMIT()  asm volatile("cp.async.commit_group;" ::: "memory")
#define CP_WAIT(N)   asm volatile("cp.async.wait_group %0;" :: "n"(N) : "memory")
__device__ __forceinline__ void barx128(int id) {
    asm volatile("bar.sync %0, 128;" :: "r"(id) : "memory");
}

// ---------- HMMA plumbing (baseline PTX, works on plain sm_103) ----------
__device__ __forceinline__ void ldsm4(uint32_t* r, uint32_t a) {
    asm volatile("ldmatrix.sync.aligned.m8n8.x4.shared.b16 {%0,%1,%2,%3}, [%4];"
                 : "=r"(r[0]), "=r"(r[1]), "=r"(r[2]), "=r"(r[3]) : "r"(a));
}
__device__ __forceinline__ void ldsm2(uint32_t* r, uint32_t a) {
    asm volatile("ldmatrix.sync.aligned.m8n8.x2.shared.b16 {%0,%1}, [%2];"
                 : "=r"(r[0]), "=r"(r[1]) : "r"(a));
}
__device__ __forceinline__ void mma16816(float* d, const uint32_t* a, const uint32_t* b) {
    asm volatile("mma.sync.aligned.m16n8k16.row.col.f32.bf16.bf16.f32 "
                 "{%0,%1,%2,%3}, {%4,%5,%6,%7}, {%8,%9}, {%0,%1,%2,%3};"
                 : "+f"(d[0]), "+f"(d[1]), "+f"(d[2]), "+f"(d[3])
                 : "r"(a[0]), "r"(a[1]), "r"(a[2]), "r"(a[3]), "r"(b[0]), "r"(b[1]));
}

// ============================================================
// split kernels: fp32 -> bf16 hi + lo
// ============================================================
__global__ __launch_bounds__(512)
void wsplit_kernel(const float* __restrict__ Win, const float* __restrict__ Wout,
                   __nv_bfloat16* __restrict__ wh, __nv_bfloat16* __restrict__ wl)
{
    int gid = blockIdx.x * 512 + threadIdx.x;     // 131072
    int mat = gid >> 16;
    int idx = gid & 65535;
    float x = (mat == 0) ? Win[idx] : Wout[idx];
    __nv_bfloat16 hi = __float2bfloat16_rn(x);
    __nv_bfloat16 lo = __float2bfloat16_rn(x - __bfloat162float(hi));
    wh[gid] = hi;
    wl[gid] = lo;
}

__global__ __launch_bounds__(512)
void asplit_kernel(const float* __restrict__ A,
                   __nv_bfloat16* __restrict__ ah, __nv_bfloat16* __restrict__ al)
{
    int gid = blockIdx.x * 512 + threadIdx.x;     // 262144 (x4 floats)
    float4 v = reinterpret_cast<const float4*>(A)[gid];
    __nv_bfloat16 h0 = __float2bfloat16_rn(v.x);
    __nv_bfloat16 h1 = __float2bfloat16_rn(v.y);
    __nv_bfloat16 h2 = __float2bfloat16_rn(v.z);
    __nv_bfloat16 h3 = __float2bfloat16_rn(v.w);
    __nv_bfloat162 hp0, hp1, lp0, lp1;
    hp0.x = h0; hp0.y = h1; hp1.x = h2; hp1.y = h3;
    lp0.x = __float2bfloat16_rn(v.x - __bfloat162float(h0));
    lp0.y = __float2bfloat16_rn(v.y - __bfloat162float(h1));
    lp1.x = __float2bfloat16_rn(v.z - __bfloat162float(h2));
    lp1.y = __float2bfloat16_rn(v.w - __bfloat162float(h3));
    reinterpret_cast<__nv_bfloat162*>(ah)[gid * 2]     = hp0;
    reinterpret_cast<__nv_bfloat162*>(ah)[gid * 2 + 1] = hp1;
    reinterpret_cast<__nv_bfloat162*>(al)[gid * 2]     = lp0;
    reinterpret_cast<__nv_bfloat162*>(al)[gid * 2 + 1] = lp1;
}

// ============================================================
// HMMA GEMM: C[m,n] = sum_k A[m,k]*W[n,k] + bias[n]
// CTA M=128 x N=64, 256 thr = 4 m-warps x 2 n-warps (warp 32x32).
// W hi/lo full-K resident in smem (row stride 528B, LDSM
// conflict-free). A hi/lo streamed in BK=32 chunks, 4-stage
// cp.async pipeline (row stride 80B, conflict-free).
// 3 passes: Ah*Wh + Ah*Wl + Al*Wh (fp32 accum).
// ============================================================
static constexpr int WH_OFF = 0;
static constexpr int WL_OFF = 33792;                 // 64*528
static constexpr int AB_OFF = 67584;
static constexpr int A_ST   = 10240;                 // 128*80
static constexpr int SMEM_GEMM = AB_OFF + 8 * A_ST;  // 149504

__global__ __launch_bounds__(256)
void gemm_tc_kernel(const __nv_bfloat16* __restrict__ ah,
                    const __nv_bfloat16* __restrict__ al,
                    const __nv_bfloat16* __restrict__ wh,
                    const __nv_bfloat16* __restrict__ wl,
                    const float* __restrict__ bias, float* __restrict__ C)
{
    extern __shared__ __align__(16) char smem[];
    const uint32_t sb = (uint32_t)__cvta_generic_to_shared(smem);
    const int t    = threadIdx.x;
    const int lane = t & 31;
    const int w    = t >> 5;
    const int mw   = w & 3;          // m-warp (32 rows)
    const int nw   = w >> 2;         // n-warp (32 cols)
    const int n0   = blockIdx.x * 64;
    const int m0   = blockIdx.y * 128;

    // ---- W hi/lo load: 4096 granules (2 mats x 64 rows x 32 granule-cols),
    //      16 per thread
#pragma unroll
    for (int i = 0; i < 16; i++) {
        int gi = t + i * 256;
        int mat = gi >> 11, r = gi & 2047;
        int row = r >> 5, gc = r & 31;
        const __nv_bfloat16* src = (mat ? wl : wh) + (size_t)(n0 + row) * Dc + gc * 8;
        cp_async16(smem + (mat ? WL_OFF : WH_OFF) + row * 528 + gc * 16, src);
    }

    auto load_chunk = [&](int c, int s) {
#pragma unroll
        for (int i = 0; i < 4; i++) {
            int gi = t + i * 256;
            int mat = gi >> 9, r = gi & 511;
            int row = r >> 2, gc = r & 3;
            const __nv_bfloat16* src = (mat ? al : ah) + (size_t)(m0 + row) * Dc + c * 32 + gc * 8;
            cp_async16(smem + AB_OFF + (s * 2 + mat) * A_ST + row * 80 + gc * 16, src);
        }
        CP_COMMIT();
    };
    load_chunk(0, 0);    // group0 = W + A0
    load_chunk(1, 1);
    load_chunk(2, 2);

    float acc[2][4][4];
#pragma unroll
    for (int mf = 0; mf < 2; mf++)
#pragma unroll
        for (int nf = 0; nf < 4; nf++)
#pragma unroll
            for (int j = 0; j < 4; j++) acc[mf][nf][j] = 0.f;

    for (int c = 0; c < 8; c++) {
        CP_WAIT(2);
        __syncthreads();
        if (c + 3 < 8) load_chunk(c + 3, (c + 3) & 3);
        else           CP_COMMIT();

        const int s = c & 3;
        const uint32_t ahb = sb + AB_OFF + (s * 2) * A_ST;
#pragma unroll
        for (int ks = 0; ks < 2; ks++) {
            uint32_t Ah[2][4], Al[2][4], Bh[4][2], Bl[4][2];
            const int arow = ((lane >> 3) & 1) * 8 + (lane & 7);
            const int acol = ks * 16 + (lane >> 4) * 8;
#pragma unroll
            for (int mf = 0; mf < 2; mf++) {
                uint32_t ad = ahb + (mw * 32 + mf * 16 + arow) * 80 + acol * 2;
                ldsm4(Ah[mf], ad);
                ldsm4(Al[mf], ad + A_ST);
            }
            const int bcol = c * 32 + ks * 16 + ((lane >> 3) & 1) * 8;
            const int brow = lane & 7;
#pragma unroll
            for (int nf = 0; nf < 4; nf++) {
                uint32_t bd = sb + WH_OFF + (nw * 32 + nf * 8 + brow) * 528 + bcol * 2;
                ldsm2(Bh[nf], bd);
                ldsm2(Bl[nf], bd + WL_OFF);
            }
#pragma unroll
            for (int mf = 0; mf < 2; mf++)
#pragma unroll
                for (int nf = 0; nf < 4; nf++) {
                    mma16816(acc[mf][nf], Ah[mf], Bh[nf]);
                    mma16816(acc[mf][nf], Ah[mf], Bl[nf]);
                    mma16816(acc[mf][nf], Al[mf], Bh[nf]);
                }
        }
    }

    // ---- epilogue: bias + STG (mma C layout: lane gr=L>>2, ct=L&3)
    const int gr = lane >> 2, ct = lane & 3;
#pragma unroll
    for (int mf = 0; mf < 2; mf++) {
        const int r0 = m0 + mw * 32 + mf * 16 + gr;
#pragma unroll
        for (int nf = 0; nf < 4; nf++) {
            const int col = n0 + nw * 32 + nf * 8 + ct * 2;
            float b0 = bias[col], b1 = bias[col + 1];
            float2 v0 = make_float2(acc[mf][nf][0] + b0, acc[mf][nf][1] + b1);
            float2 v1 = make_float2(acc[mf][nf][2] + b0, acc[mf][nf][3] + b1);
            *reinterpret_cast<float2*>(C + (size_t)r0 * Dc + col) = v0;
            *reinterpret_cast<float2*>(C + (size_t)(r0 + 8) * Dc + col) = v1;
        }
    }
}

// ============================================================
// attn (R13, best known): 512 threads = 4 k-quarters x 128,
// qpt=4, 4-stage cp.async pipeline.
// ============================================================
static constexpr int KCq   = 4;
static constexpr int NSTG  = 4;
static constexpr int FEAT_B = KCq * Dc;
static constexpr int MSG_W  = 68;
static constexpr int MSG_B  = 32 * MSG_W;
static constexpr int ADJ_B  = 32 * KCq;
static constexpr int FEAT_T = 4 * NSTG * FEAT_B;
static constexpr int MSG_T  = 4 * NSTG * MSG_B;
static constexpr int ADJ_T  = 4 * NSTG * ADJ_B;
static constexpr int SMEM_ATTN = (FEAT_T + MSG_T + ADJ_T) * 4;

__global__ __launch_bounds__(512)
void attn_kernel(const float* __restrict__ messages, const int* __restrict__ adj,
                 float* __restrict__ outp)
{
    extern __shared__ __align__(16) float smemF[];
    float* featA = smemF;
    float* msgA  = smemF + FEAT_T;
    int*   adjA  = (int*)(smemF + FEAT_T + MSG_T);

    const int t  = threadIdx.x;
    const int quarter = t >> 7;
    const int lt = t & 127;
    const int h  = lt & 15;
    const int qg = lt >> 4;
    const int b  = blockIdx.y;
    const int qb0 = blockIdx.x * 32;
    const int qbase = qb0 + qg * 4;

    const float4* msgG  = (const float4*)(messages + (size_t)(b * NQ + qb0) * NKV * Hc);
    const int*    adjG  = adj + (size_t)(b * NQ + qb0) * NKV;
    const float4* proj4 = (const float4*)(g_proj + (size_t)b * NKV * Dc);

    float l[4]  = {0.f, 0.f, 0.f, 0.f};
    float s2[4] = {0.f, 0.f, 0.f, 0.f};
    u64 acc[4][8];
#pragma unroll
    for (int qi = 0; qi < 4; qi++)
#pragma unroll
        for (int j = 0; j < 8; j++) acc[qi][j] = pack2(0.f, 0.f);

    auto load_stage = [&](int c, int s) {
        const int k0 = c * KCq;
        float* fb = featA + (quarter * NSTG + s) * FEAT_B;
#pragma unroll
        for (int i = 0; i < 2; i++) {
            int lin = lt + i * 128;
            int kk = lin >> 6, g = lin & 63;
            int hh = g >> 2, j = g & 3;
            int dstf4 = j * (KCq * 16) + kk * 16 + (hh ^ (2 * j));
            cp_async16(fb + dstf4 * 4, &proj4[(size_t)(k0 + kk) * 64 + g]);
        }
        float* mb = msgA + (quarter * NSTG + s) * MSG_B;
#pragma unroll
        for (int i = 0; i < 4; i++) {
            int lin = lt + i * 128;
            int q = lin >> 4, g16 = lin & 15;
            cp_async16(mb + q * MSG_W + g16 * 4,
                       &msgG[((size_t)q * NKV + k0 + (g16 >> 2)) * 4 + (g16 & 3)]);
        }
        if (lt < 32) {
            cp_async16(adjA + (quarter * NSTG + s) * ADJ_B + lt * 4,
                       adjG + (size_t)lt * NKV + k0);
        }
        CP_COMMIT();
    };

    const float L2E = 1.4426950408889634f;
    const int NCI = NKV / KCq / 4;

    load_stage(quarter, 0);
    load_stage(4 + quarter, 1);
    load_stage(8 + quarter, 2);

    for (int ci = 0; ci < NCI; ci++) {
        const int s = ci & (NSTG - 1);
        CP_WAIT(2);
        barx128(quarter + 1);
        if (ci + 3 < NCI) load_stage(4 * (ci + 3) + quarter, (ci + 3) & (NSTG - 1));
        else              CP_COMMIT();

        const float* fb = featA + (quarter * NSTG + s) * FEAT_B;
        const float* mb = msgA  + (quarter * NSTG + s) * MSG_B;
        const int*   ab = adjA  + (quarter * NSTG + s) * ADJ_B;

        int4 av[4];
#pragma unroll
        for (int qi = 0; qi < 4; qi++)
            av[qi] = *reinterpret_cast<const int4*>(&ab[(qg * 4 + qi) * 4]);
#pragma unroll
        for (int u = 0; u < 4; u++) {
            u64 f[8];
#pragma unroll
            for (int j = 0; j < 4; j++) {
                float4 fv = *reinterpret_cast<const float4*>(
                    &fb[(j * (KCq * 16) + u * 16 + (h ^ (2 * j))) * 4]);
                f[2 * j]     = pack2(fv.x, fv.y);
                f[2 * j + 1] = pack2(fv.z, fv.w);
            }
#pragma unroll
            for (int qi = 0; qi < 4; qi++) {
                float mv = mb[(qg * 4 + qi) * MSG_W + u * 16 + h];
                int a = (&av[qi].x)[u];
                float lg = fmaf(mv, L2E, (a > 0) ? 0.f : -2e9f);
                float p = ex2f(lg);
                l[qi] += p;
                s2[qi] = fmaf(p, p, s2[qi]);
                u64 pp = pack2(p, p);
#pragma unroll
                for (int j = 0; j < 8; j++)
                    acc[qi][j] = fma2(pp, f[j], acc[qi][j]);
            }
        }
    }

    __syncthreads();
    float* redS = msgA;
    if (quarter > 0) {
        float* sp = redS + ((size_t)(quarter - 1) * 128 + lt) * 73;
#pragma unroll
        for (int qi = 0; qi < 4; qi++) {
#pragma unroll
            for (int j = 0; j < 8; j++)
                unpack2(acc[qi][j], sp[qi * 18 + 2 * j], sp[qi * 18 + 2 * j + 1]);
            sp[qi * 18 + 16] = l[qi];
            sp[qi * 18 + 17] = s2[qi];
        }
    }
    __syncthreads();
    if (quarter == 0) {
#pragma unroll
        for (int qi = 0; qi < 4; qi++) {
            float v[16];
#pragma unroll
            for (int j = 0; j < 8; j++) unpack2(acc[qi][j], v[2 * j], v[2 * j + 1]);
            float lsum = l[qi], s2sum = s2[qi];
#pragma unroll
            for (int r = 0; r < 3; r++) {
                const float* sp = redS + ((size_t)r * 128 + lt) * 73 + qi * 18;
#pragma unroll
                for (int j = 0; j < 16; j++) v[j] += sp[j];
                lsum  += sp[16];
                s2sum += sp[17];
            }
            float wsc = sqrtf(s2sum) / (lsum * lsum);
            float* o = outp + (size_t)(b * NQ + qbase + qi) * Dc + h * 16;
#pragma unroll
            for (int j = 0; j < 4; j++) {
                float4 ov = make_float4(v[4*j] * wsc, v[4*j+1] * wsc,
                                        v[4*j+2] * wsc, v[4*j+3] * wsc);
                *reinterpret_cast<float4*>(o + 4 * j) = ov;
            }
        }
    }
}

// ============================================================
extern "C" void kernel_launch(void* const* d_in, const int* in_sizes, int n_in,
                              void* d_out, int out_size)
{
    const float* v_inv    = (const float*)d_in[0];
    const float* messages = (const float*)d_in[1];
    const int*   adjm     = (const int*)d_in[2];
    const float* W_in     = (const float*)d_in[3];
    const float* b_in     = (const float*)d_in[4];
    const float* W_out    = (const float*)d_in[5];
    const float* b_out    = (const float*)d_in[6];
    float* out = (float*)d_out;

    float *p_proj = nullptr, *p_attn = nullptr;
    __nv_bfloat16 *p_wh = nullptr, *p_wl = nullptr, *p_ah = nullptr, *p_al = nullptr;
    cudaGetSymbolAddress((void**)&p_proj, g_proj);
    cudaGetSymbolAddress((void**)&p_attn, g_attn);
    cudaGetSymbolAddress((void**)&p_wh,   g_wh);
    cudaGetSymbolAddress((void**)&p_wl,   g_wl);
    cudaGetSymbolAddress((void**)&p_ah,   g_ah);
    cudaGetSymbolAddress((void**)&p_al,   g_al);

    cudaFuncSetAttribute(attn_kernel, cudaFuncAttributeMaxDynamicSharedMemorySize, SMEM_ATTN);
    cudaFuncSetAttribute(gemm_tc_kernel, cudaFuncAttributeMaxDynamicSharedMemorySize, SMEM_GEMM);

    // 0) split weights once
    wsplit_kernel<<<256, 512>>>(W_in, W_out, p_wh, p_wl);

    // 1) proj = v_inv @ W_in^T + b_in   (HMMA bf16 3-split)
    asplit_kernel<<<512, 512>>>(v_inv, p_ah, p_al);
    gemm_tc_kernel<<<dim3(4, 32), 256, SMEM_GEMM>>>(p_ah, p_al, p_wh, p_wl, b_in, p_proj);

    // 2) fused attention -> g_attn
    {
        dim3 grid(NQ / 32, Bc);
        attn_kernel<<<grid, 512, SMEM_ATTN>>>(messages, adjm, p_attn);
    }

    // 3) out = g_attn @ W_out^T + b_out (HMMA bf16 3-split)
    asplit_kernel<<<512, 512>>>(p_attn, p_ah, p_al);
    gemm_tc_kernel<<<dim3(4, 32), 256, SMEM_GEMM>>>(p_ah, p_al, p_wh + Dc * Dc,
                                                    p_wl + Dc * Dc, b_out, out);
}